// round 11
// baseline (speedup 1.0000x reference)
#include <cuda_runtime.h>
#include <math.h>
#include <stdint.h>

#define E_N     100000
#define NODES   10000
#define DIMIN   72
#define NR      1216
#define HID     100
#define NY      25
#define NT_TAB  513            // radial table nodes over [0.7, 3.2], h = 2.5/512

// ---------------- scratch (device globals; zero-init) ----------------
__device__ float    g_T [(size_t)NT_TAB * NR];   // radial table f(d_j)
__device__ float    g_Yb[(size_t)E_N * NY];
__device__ float    g_CG[1225];
__device__ float    g_K [25];
__device__ uint32_t g_planTY[259];
__device__ uint32_t g_planG [552];

// ---------------- triple metadata (19 (lo,li,l) triples) ----------------
__constant__ int TRIP_LO[19]   = {0,0,0, 1,1,1,1,1,1,1, 2,2,2,2,2,2,2,2,2};
__constant__ int TRIP_LI[19]   = {0,1,2, 0,1,1,1,2,2,2, 0,1,1,1,2,2,2,2,2};
__constant__ int TRIP_L [19]   = {0,1,2, 1,0,1,2,1,2,3, 2,1,2,3,0,1,2,3,4};
__constant__ int TRIP_CGO[19]  = {0,1,10, 35,44,53,80,125,170,245, 350,375,420,495,600,625,700,825,1000};
__constant__ int TRIP_RB[19]   = {0,64,128, 192,256,256,256,448,448,448, 640,704,704,704,896,896,896,896,896};
__constant__ int TRIP_FB[19]   = {0,8,32, 0,8,8,8,32,32,32, 0,8,8,8,32,32,32,32,32};
__constant__ int TRIP_KK[19]   = {0,0,0, 0,0,1,2,0,1,2, 0,0,1,2,0,1,2,3,4};
__constant__ int TRIP_NL[19]   = {1,1,1, 1,3,3,3,3,3,3, 1,3,3,3,5,5,5,5,5};
__constant__ int TRIP_NP[19]   = {1,1,1, 3,3,3,3,3,3,3, 5,5,5,5,5,5,5,5,5};
__constant__ int TRIP_NQ[19]   = {1,3,5, 1,3,3,3,5,5,5, 1,3,3,3,5,5,5,5,5};
__constant__ int TY_OFF[20] = {0,1,4,9, 12,21,30,39,54,69, 84,89,104,119,134,159,184,209,234, 259};
__constant__ int G_OFF [20] = {0,8,16, 24,48,72,96,120,144,168, 192,232,272,312,352,392,432,472,512, 552};
__constant__ int TSTART[4] = {0, 3, 10, 19};

// ---------------- CG math (doubles) ----------------
__device__ __forceinline__ double dfact(int n) {
    const double f[11] = {1.,1.,2.,6.,24.,120.,720.,5040.,40320.,362880.,3628800.};
    return f[n];
}
__device__ double w3j(int j1,int j2,int j3,int m1,int m2,int m3) {
    if (m1 + m2 + m3 != 0) return 0.0;
    if (j3 < abs(j1 - j2) || j3 > j1 + j2) return 0.0;
    if (abs(m1) > j1 || abs(m2) > j2 || abs(m3) > j3) return 0.0;
    double pre = sqrt(dfact(j1+j2-j3)*dfact(j1-j2+j3)*dfact(-j1+j2+j3)/dfact(j1+j2+j3+1)
                 *dfact(j1+m1)*dfact(j1-m1)*dfact(j2+m2)*dfact(j2-m2)*dfact(j3+m3)*dfact(j3-m3));
    int kmin = max(0, max(j2 - j3 - m1, j1 - j3 + m2));
    int kmax = min(j1 + j2 - j3, min(j1 - m1, j2 + m2));
    double s = 0.0;
    for (int k = kmin; k <= kmax; ++k) {
        double den = dfact(k)*dfact(j1+j2-j3-k)*dfact(j1-m1-k)*dfact(j2+m2-k)
                    *dfact(j3-j2+m1+k)*dfact(j3-j1-m2+k);
        s += ((k & 1) ? -1.0 : 1.0) / den;
    }
    int ph = j1 - j2 - m3;
    return ((ph & 1) ? -1.0 : 1.0) * pre * s;
}
__device__ __forceinline__ double2 Uent(int l, int a, int mc) {
    const double is2 = 0.70710678118654752440;
    int mr = a - l, m = mc - l;
    double2 z; z.x = 0.0; z.y = 0.0;
    if (mr == 0) { if (m == 0) z.x = 1.0; }
    else if (mr > 0) {
        if (m == mr)       z.x = ((mr & 1) ? -1.0 : 1.0) * is2;
        else if (m == -mr) z.x = is2;
    } else {
        int ma = -mr;
        if (m == mr)      z.y = is2;
        else if (m == ma) z.y = -((ma & 1) ? -1.0 : 1.0) * is2;
    }
    return z;
}
__device__ __forceinline__ double2 cmul(double2 a, double2 b) {
    double2 r; r.x = a.x*b.x - a.y*b.y; r.y = a.x*b.y + a.y*b.x; return r;
}

// warp-per-entry CG init; block 0 also fills K norms and plan tables
__global__ void cg_init_kernel() {
    int gw = (blockIdx.x * blockDim.x + threadIdx.x) >> 5;
    int lane = threadIdx.x & 31;

    if (blockIdx.x == 0) {
        for (int t = threadIdx.x; t < 25 + 259 + 552; t += 256) {
            if (t < 25) {
                int c = t;
                int l = 0;
                while ((l+1)*(l+1) <= c) l++;
                int m = c - l*l - l;
                int am = abs(m);
                double K = sqrt((2.0*l + 1.0) / (4.0 * 3.14159265358979323846) * dfact(l - am) / dfact(l + am));
                g_K[c] = (float)(m == 0 ? K : sqrt(2.0) * K);
            } else if (t < 25 + 259) {
                int item = t - 25;
                int tr = 0;
                while (item >= TY_OFF[tr + 1]) ++tr;
                int local = item - TY_OFF[tr];
                int np = TRIP_NP[tr], nq = TRIP_NQ[tr];
                int q = local / np, p = local % np;
                int l = TRIP_L[tr], nr2 = 2 * l + 1;
                uint32_t cgbase = (uint32_t)(TRIP_CGO[tr] + (p * nq + q) * nr2);
                g_planTY[item] = cgbase | ((uint32_t)(l * l) << 12) | ((uint32_t)nr2 << 17);
            } else {
                int item = t - 25 - 259;
                int tr = 0;
                while (item >= G_OFF[tr + 1]) ++tr;
                int local = item - G_OFF[tr];
                int np = TRIP_NP[tr], nq = TRIP_NQ[tr];
                int v = local / np, p = local % np;
                uint32_t fbase = (uint32_t)(TRIP_FB[tr] + v * nq);
                uint32_t tyb   = (uint32_t)(TY_OFF[tr] + p);
                g_planG[item] = fbase | ((uint32_t)nq << 7) | (tyb << 10) | ((uint32_t)np << 19);
            }
        }
    }

    if (gw >= 1225) return;
    int idx = gw;
    int t = 0;
    for (t = 0; t < 19; ++t) {
        int sz = (2*TRIP_LO[t]+1) * (2*TRIP_LI[t]+1) * (2*TRIP_L[t]+1);
        if (idx < TRIP_CGO[t] + sz) break;
    }
    int lo = TRIP_LO[t], li = TRIP_LI[t], l = TRIP_L[t];
    int local = idx - TRIP_CGO[t];
    int nq = 2*li + 1, nr = 2*l + 1;
    int p = local / (nq * nr);
    int q = (local / nr) % nq;
    int r = local % nr;
    int n1 = 2*lo + 1;
    int total = n1 * nq * nr;
    double s = 0.0;
    for (int it = lane; it < total; it += 32) {
        int m  = it / (nq * nr);
        int rem = it % (nq * nr);
        int n  = rem / nr;
        int pp = rem % nr;
        double2 u1 = Uent(lo, p, m);
        if (u1.x == 0.0 && u1.y == 0.0) continue;
        double2 u2 = Uent(li, q, n);
        if (u2.x == 0.0 && u2.y == 0.0) continue;
        double2 u3 = Uent(l, r, pp);
        if (u3.x == 0.0 && u3.y == 0.0) continue;
        double w = w3j(lo, li, l, m - lo, n - li, pp - l);
        if (w == 0.0) continue;
        double2 u = cmul(cmul(u1, u2), u3);
        s += (u.x + u.y) * w;
    }
#pragma unroll
    for (int off = 16; off > 0; off >>= 1)
        s += __shfl_down_sync(0xffffffffu, s, off);
    if (lane == 0) g_CG[idx] = (float)s;
}

// ---------------- radial table: one block per node, exact fp32 MLP ----------------
__global__ __launch_bounds__(256)
void table_kernel(const float* __restrict__ W0, const float* __restrict__ W1,
                  const float* __restrict__ W2, const float* __restrict__ W3) {
    __shared__ float ha[HID], hbuf[HID], hb[10];
    const int node = blockIdx.x;
    const int t = threadIdx.x;
    const float d = 0.7f + 2.5f * (float)node / (float)(NT_TAB - 1);

    if (t < 10) {
        float c = 0.7f + (2.5f / 9.0f) * (float)t;
        float tt = (d - c) * 4.5f;
        hb[t] = expf(-tt * tt) * (1.0f / 1.423085244900308f);
    }
    __syncthreads();
    if (t < HID) {
        float s = 0.0f;
#pragma unroll
        for (int b = 0; b < 10; ++b) s += hb[b] * W0[b * HID + t];
        s *= 0.31622776601683794f;
        ha[t] = s / (1.0f + expf(-s));
    }
    __syncthreads();
    if (t < HID) {
        float s = 0.0f;
        for (int k = 0; k < HID; ++k) s += ha[k] * W1[k * HID + t];
        s *= 0.1f;
        hbuf[t] = s / (1.0f + expf(-s));
    }
    __syncthreads();
    if (t < HID) {
        float s = 0.0f;
        for (int k = 0; k < HID; ++k) s += hbuf[k] * W2[k * HID + t];
        s *= 0.1f;
        ha[t] = s / (1.0f + expf(-s));
    }
    __syncthreads();
    for (int o = t; o < NR; o += 256) {
        float s = 0.0f;
        for (int k = 0; k < HID; ++k) s += ha[k] * W3[(size_t)k * NR + o];
        g_T[(size_t)node * NR + o] = 0.1f * s;
    }
}

// ---------------- prep: spherical harmonics only (warp per edge) ----------------
__global__ __launch_bounds__(256)
void prep_kernel(const float* __restrict__ rel) {
    int e = blockIdx.x * 8 + (threadIdx.x >> 5);
    int lane = threadIdx.x & 31;
    if (e >= E_N || lane >= 25) return;

    float vx = rel[e*3+0], vy = rel[e*3+1], vz = rel[e*3+2];
    float r = sqrtf(vx*vx + vy*vy + vz*vz);
    float inv = 1.0f / fmaxf(r, 1e-9f);
    float x = vx * inv, y = vy * inv, z = vz * inv;

    float A[5], B[5];
    A[0] = 1.0f; B[0] = 0.0f;
#pragma unroll
    for (int m = 1; m <= 4; ++m) {
        A[m] = x * A[m-1] - y * B[m-1];
        B[m] = x * B[m-1] + y * A[m-1];
    }
    float p[5][5];
    p[0][0] = 1.0f;
#pragma unroll
    for (int m = 0; m <= 4; ++m) {
        if (m > 0) p[m][m] = -(2.0f * m - 1.0f) * p[m-1][m-1];
        if (m + 1 <= 4) p[m+1][m] = (2.0f * m + 1.0f) * z * p[m][m];
#pragma unroll
        for (int l = m + 2; l <= 4; ++l)
            p[l][m] = ((2.0f*l - 1.0f) * z * p[l-1][m] - (l + m - 1.0f) * p[l-2][m]) / (float)(l - m);
    }
    float val = 0.0f;
    int c = 0;
#pragma unroll
    for (int l = 0; l <= 4; ++l) {
#pragma unroll
        for (int m = -4; m <= 4; ++m) {
            if (m < -l || m > l) continue;
            int am = m < 0 ? -m : m;
            if (c == lane) {
                float gk = g_K[c];
                if (m == 0)      val = gk * p[l][0];
                else if (m > 0)  val = gk * p[l][am] * A[am];
                else             val = gk * p[l][am] * B[am];
            }
            c++;
        }
    }
    g_Yb[(size_t)e * NY + lane] = val;
}

// ---------------- zero output ----------------
__global__ void zero_kernel(float* out, int n) {
    int i = blockIdx.x * blockDim.x + threadIdx.x;
    if (i < n) out[i] = 0.0f;
}

// ---------------- message: float4 cubic-interp R from table + contraction + scatter ----------------
__global__ __launch_bounds__(128)
void msg_kernel(const int* __restrict__ ei, const float* __restrict__ x,
                const float* __restrict__ dist, float* __restrict__ out) {
    __shared__ float Rs[NR];
    __shared__ float Fs[DIMIN];
    __shared__ float Ys[NY];
    __shared__ float tYs[259];
    __shared__ float Gsm[552];

    const int e = blockIdx.x;
    const int t = threadIdx.x;
    const int src = ei[e];
    const int dst = ei[E_N + e];

    // cubic Lagrange interpolation of the radial table (vectorized float4)
    {
        float u = (dist[e] - 0.7f) * ((float)(NT_TAB - 1) / 2.5f);
        int i0 = (int)floorf(u);
        i0 = min(max(i0, 1), NT_TAB - 3);
        float tt = u - (float)i0;
        float tm = tt - 1.0f, tp = tt + 1.0f, tm2 = tt - 2.0f;
        float w0 = -tt * tm * tm2 * (1.0f / 6.0f);
        float w1 =  tp * tm * tm2 * 0.5f;
        float w2 = -tp * tt * tm2 * 0.5f;
        float w3 =  tp * tt * tm  * (1.0f / 6.0f);
        const float4* __restrict__ T0 = (const float4*)(g_T + (size_t)(i0 - 1) * NR);
        const float4* __restrict__ T1 = (const float4*)(g_T + (size_t)(i0    ) * NR);
        const float4* __restrict__ T2 = (const float4*)(g_T + (size_t)(i0 + 1) * NR);
        const float4* __restrict__ T3 = (const float4*)(g_T + (size_t)(i0 + 2) * NR);
        float4* __restrict__ Rd = (float4*)Rs;
#pragma unroll 3
        for (int i = t; i < NR / 4; i += 128) {
            float4 a = __ldg(T0 + i);
            float4 b = __ldg(T1 + i);
            float4 c = __ldg(T2 + i);
            float4 d4 = __ldg(T3 + i);
            float4 r;
            r.x = w0 * a.x + w1 * b.x + w2 * c.x + w3 * d4.x;
            r.y = w0 * a.y + w1 * b.y + w2 * c.y + w3 * d4.y;
            r.z = w0 * a.z + w1 * b.z + w2 * c.z + w3 * d4.z;
            r.w = w0 * a.w + w1 * b.w + w2 * c.w + w3 * d4.w;
            Rd[i] = r;
        }
    }
    if (t < DIMIN) Fs[t] = x[(size_t)src * DIMIN + t];
    if (t < NY) Ys[t] = g_Yb[(size_t)e * NY + t];
    __syncthreads();

    // pass 1: tY
    for (int item = t; item < 259; item += 128) {
        uint32_t plan = __ldg(&g_planTY[item]);
        int cg  = plan & 0xFFF;
        int yb  = (plan >> 12) & 31;
        int nr2 = plan >> 17;
        float s = 0.0f;
        for (int r = 0; r < nr2; ++r)
            s += __ldg(&g_CG[cg + r]) * Ys[yb + r];
        tYs[item] = s;
    }
    __syncthreads();

    // pass 2: G
    for (int item = t; item < 552; item += 128) {
        uint32_t plan = __ldg(&g_planG[item]);
        int fb  = plan & 127;
        int nq  = (plan >> 7) & 7;
        int tyb = (plan >> 10) & 511;
        int np  = (plan >> 19) & 7;
        float s = 0.0f;
        for (int q = 0; q < nq; ++q)
            s += Fs[fb + q] * tYs[tyb + q * np];
        Gsm[item] = s;
    }
    __syncthreads();

    // pass 3: contract with R, scatter
    if (t < DIMIN) {
        int o = t;
        int i, u, p, np;
        if (o < 8)       { i = 0; u = o;            p = 0;            np = 1; }
        else if (o < 32) { i = 1; u = (o - 8) / 3;  p = (o - 8) % 3;  np = 3; }
        else             { i = 2; u = (o - 32) / 5; p = (o - 32) % 5; np = 5; }
        float acc = 0.0f;
        for (int tr = TSTART[i]; tr < TSTART[i + 1]; ++tr) {
            int nl = TRIP_NL[tr], kk = TRIP_KK[tr];
            int rb = TRIP_RB[tr] + u * 8 * nl + kk;
            int gb = G_OFF[tr] + p;
            float s = 0.0f;
#pragma unroll
            for (int v = 0; v < 8; ++v)
                s += Rs[rb + v * nl] * Gsm[gb + v * np];
            acc += s;
        }
        const float nse[3] = {24.0f, 56.0f, 72.0f};
        float normi = 3.5449077018110318f * sqrtf(2.0f * i + 1.0f) * rsqrtf(nse[i]);
        atomicAdd(&out[(size_t)dst * DIMIN + o], acc * normi);
    }
}

// ---------------- launch ----------------
extern "C" void kernel_launch(void* const* d_in, const int* in_sizes, int n_in,
                              void* d_out, int out_size) {
    const int*   ei   = (const int*)  d_in[0];
    const float* x    = (const float*)d_in[1];
    const float* dist = (const float*)d_in[2];
    const float* rel  = (const float*)d_in[3];
    const float* W0   = (const float*)d_in[4];
    const float* W1   = (const float*)d_in[5];
    const float* W2   = (const float*)d_in[6];
    const float* W3   = (const float*)d_in[7];
    float* out = (float*)d_out;

    cg_init_kernel<<<154, 256>>>();
    table_kernel<<<NT_TAB, 256>>>(W0, W1, W2, W3);
    prep_kernel<<<(E_N + 7) / 8, 256>>>(rel);
    zero_kernel<<<(out_size + 255) / 256, 256>>>(out, out_size);
    msg_kernel<<<E_N, 128>>>(ei, x, dist, out);
}